// round 9
// baseline (speedup 1.0000x reference)
#include <cuda_runtime.h>
#include <cuda_fp16.h>
#include <cstdint>

// out[b,n] = sum_{c,hw} x[b,c,hw]*W_s[n,hw]*W_d[n,c] + W_b[n]
// GEMM Y[(b,c),n] = X[8192,3136] @ Ws[1024,3136]^T, single-fp16 mma.sync,
// fp32 accum, fused W_d epilogue, K-split 4 via atomicAdd merge.
// R8: persistent CTAs (296 = 148 SMs x 2) with a global load cursor that
// runs 2 chunks ahead ACROSS work-unit boundaries: next tile's loads are in
// flight during the current tile's tail + epilogue. Removes 2048 pipeline
// fills, wave transitions, and most launch overhead (R7 lesson: wave
// quantization is soft; per-tile fixed costs are the real residual).

#define K_DIM 3136
#define C_DIM 256
#define N_DIM 1024
#define M_DIM 8192
#define BM 128
#define BN 128
#define BK 64
#define MAT_B 16384           // 128 rows * 128B
#define STAGE_B 32768         // A + B
#define SMEM_TOTAL (3 * STAGE_B)   // 98304
#define NUNITS 2048           // 64 m-tiles * 8 n-tiles * 4 k-splits
#define NCTAS 296

// ---------------- scratch (alloc-free) ----------------
__device__ __align__(256) __half g_X16[(long)M_DIM * K_DIM];
__device__ __align__(256) __half g_W16[(long)N_DIM * K_DIM];

__device__ __forceinline__ uint32_t smem_u32(const void* p) {
    uint32_t a;
    asm("{ .reg .u64 t; cvta.to.shared.u64 t, %1; cvt.u32.u64 %0, t; }"
        : "=r"(a) : "l"(p));
    return a;
}
__device__ __forceinline__ void cp_async16(uint32_t dst, const void* src) {
    asm volatile("cp.async.cg.shared.global [%0], [%1], 16;"
                 :: "r"(dst), "l"(src));
}
__device__ __forceinline__ void cp_commit() {
    asm volatile("cp.async.commit_group;" ::: "memory");
}
template <int N>
__device__ __forceinline__ void cp_wait() {
    asm volatile("cp.async.wait_group %0;" :: "n"(N) : "memory");
}
__device__ __forceinline__ void ldsm4(uint32_t& r0, uint32_t& r1, uint32_t& r2,
                                      uint32_t& r3, uint32_t a) {
    asm volatile("ldmatrix.sync.aligned.m8n8.x4.shared.b16 {%0,%1,%2,%3}, [%4];"
                 : "=r"(r0), "=r"(r1), "=r"(r2), "=r"(r3) : "r"(a));
}
__device__ __forceinline__ void mma16816(float* c, const uint32_t* a,
                                         const uint32_t* b) {
    asm volatile(
        "mma.sync.aligned.m16n8k16.row.col.f32.f16.f16.f32 "
        "{%0,%1,%2,%3}, {%4,%5,%6,%7}, {%8,%9}, {%0,%1,%2,%3};"
        : "+f"(c[0]), "+f"(c[1]), "+f"(c[2]), "+f"(c[3])
        : "r"(a[0]), "r"(a[1]), "r"(a[2]), "r"(a[3]), "r"(b[0]), "r"(b[1]));
}

// unit u: m_idx = u>>5 ; n_idx = (u>>2)&7 ; z = u&3  (z fastest -> L2 reuse)
__device__ __forceinline__ int unit_cs(int u) {
    int z = u & 3; return (z == 0) ? 0 : 13 + 12 * (z - 1);
}
__device__ __forceinline__ int unit_ce(int u) {
    return 13 + 12 * (u & 3);
}

// ---------------- fp32 -> fp16 conversion (both tensors, one launch) --------
__global__ void conv_kernel(const float* __restrict__ x,
                            const float* __restrict__ ws) {
    const long NX = (long)M_DIM * K_DIM;
    const long NW = (long)N_DIM * K_DIM;
    long i = ((long)blockIdx.x * blockDim.x + threadIdx.x) * 4;
    if (i < NX) {
        float4 v = *(const float4*)(x + i);
        __half2* d = (__half2*)(g_X16 + i);
        d[0] = __floats2half2_rn(v.x, v.y);
        d[1] = __floats2half2_rn(v.z, v.w);
    } else if (i < NX + NW) {
        long j = i - NX;
        float4 v = *(const float4*)(ws + j);
        __half2* d = (__half2*)(g_W16 + j);
        d[0] = __floats2half2_rn(v.x, v.y);
        d[1] = __floats2half2_rn(v.z, v.w);
    }
}

__global__ void init_out_kernel(const float* __restrict__ Wb,
                                float* __restrict__ out) {
    int i = blockIdx.x * blockDim.x + threadIdx.x;
    out[i] = Wb[i & (N_DIM - 1)];
}

// ---------------- persistent GEMM ----------------
// smem swizzle: 16B chunk c of row r lives at r*128 + ((c ^ (r&7))<<4).
__global__ __launch_bounds__(256, 2)
void gemm_kernel(const float* __restrict__ Wd, float* __restrict__ out) {
    extern __shared__ char smem[];
    const uint32_t sb = smem_u32(smem);
    const int tid = threadIdx.x;
    const int lane = tid & 31;
    const int warp = tid >> 5;
    const int mwarp = (warp >> 2) * 64;   // 2 warp-rows
    const int nwarp = (warp & 3) * 32;    // 4 warp-cols

    const uint32_t e = (uint32_t)(lane & 7);          // swizzle key
    const uint32_t a_row = (uint32_t)(mwarp + (lane & 15)) * 128u;
    const uint32_t b_row =
        (uint32_t)(nwarp + (lane & 7) + ((lane >> 4) & 1) * 8) * 128u;
    uint32_t akoff[4], bkoff[4];
#pragma unroll
    for (int ks = 0; ks < 4; ++ks) {
        akoff[ks] = (((uint32_t)(ks * 2 + (lane >> 4)) ^ e) << 4);
        bkoff[ks] = (((uint32_t)(ks * 2 + ((lane >> 3) & 1)) ^ e) << 4);
    }

    // ---- load cursor (CTA-uniform) ----
    int lu = blockIdx.x;            // load unit
    int lci = unit_cs(lu);          // chunk within load unit
    int lce = unit_ce(lu);
    int tc = 0;                     // total committed groups
    int tcmp = 0;                   // total computed chunks

    auto issue = [&]() {
        if (lu >= NUNITS) return;
        const int lm0 = (lu >> 5) * BM;
        const int ln0 = ((lu >> 2) & 7) * BN;
        const long k0 = (long)lci * BK;
        const uint32_t st = sb + (uint32_t)(tc % 3) * STAGE_B;
#pragma unroll
        for (int u = 0; u < 4; ++u) {
            const int lin = tid + u * 256;
            const int row = lin >> 3;
            const uint32_t c = (uint32_t)(lin & 7);
            const uint32_t soff =
                (uint32_t)(row * 128) + (((c ^ (uint32_t)(row & 7))) << 4);
            cp_async16(st + soff,
                       g_X16 + (long)(lm0 + row) * K_DIM + k0 + c * 8);
            cp_async16(st + MAT_B + soff,
                       g_W16 + (long)(ln0 + row) * K_DIM + k0 + c * 8);
        }
        cp_commit();
        ++tc;
        if (++lci == lce) {
            lu += NCTAS;
            if (lu < NUNITS) { lci = unit_cs(lu); lce = unit_ce(lu); }
        }
    };

    issue();   // prologue: 2 chunks in flight
    issue();

    for (int u = blockIdx.x; u < NUNITS; u += NCTAS) {
        const int m0 = (u >> 5) * BM;
        const int n0 = ((u >> 2) & 7) * BN;
        const int nch = unit_ce(u) - unit_cs(u);

        float acc[4][4][4];
#pragma unroll
        for (int i = 0; i < 4; ++i)
#pragma unroll
            for (int j = 0; j < 4; ++j)
#pragma unroll
                for (int k = 0; k < 4; ++k) acc[i][j][k] = 0.f;

        for (int i = 0; i < nch; ++i) {
            if (tc - tcmp >= 2) cp_wait<1>(); else cp_wait<0>();
            __syncthreads();   // chunk tcmp visible; all warps off stage tcmp%3-1
            issue();           // load 2 ahead (crosses unit boundaries)

            const uint32_t st = sb + (uint32_t)(tcmp % 3) * STAGE_B;
            const uint32_t Ab = st + a_row;
            const uint32_t Bb = st + MAT_B + b_row;
#pragma unroll
            for (int ks = 0; ks < 4; ++ks) {
                uint32_t a[4][4], b[4][2];
#pragma unroll
                for (int mi = 0; mi < 4; ++mi)
                    ldsm4(a[mi][0], a[mi][1], a[mi][2], a[mi][3],
                          Ab + (uint32_t)(mi * 16 * 128) + akoff[ks]);
#pragma unroll
                for (int seg = 0; seg < 2; ++seg)
                    ldsm4(b[2 * seg][0], b[2 * seg][1], b[2 * seg + 1][0],
                          b[2 * seg + 1][1],
                          Bb + (uint32_t)(seg * 16 * 128) + bkoff[ks]);
#pragma unroll
                for (int mi = 0; mi < 4; ++mi)
#pragma unroll
                    for (int ni = 0; ni < 4; ++ni)
                        mma16816(acc[mi][ni], a[mi], b[ni]);
            }
            ++tcmp;
        }

        // ---------------- fused epilogue (no smem: overlaps in-flight loads)
        const int b = m0 >> 8;
        const int cbase = (m0 & (C_DIM - 1)) + mwarp;
        const int g = lane >> 2;
        const int t = lane & 3;

        float p[4][2];
#pragma unroll
        for (int ni = 0; ni < 4; ++ni) { p[ni][0] = 0.f; p[ni][1] = 0.f; }

#pragma unroll
        for (int mi = 0; mi < 4; ++mi) {
            const int c0 = cbase + mi * 16 + g;
#pragma unroll
            for (int ni = 0; ni < 4; ++ni) {
                const int n = n0 + nwarp + ni * 8 + 2 * t;
#pragma unroll
                for (int j = 0; j < 2; ++j) {
                    const float w0 = __ldg(Wd + (long)(n + j) * C_DIM + c0);
                    const float w1 = __ldg(Wd + (long)(n + j) * C_DIM + c0 + 8);
                    p[ni][j] += acc[mi][ni][j] * w0 + acc[mi][ni][j + 2] * w1;
                }
            }
        }
#pragma unroll
        for (int ni = 0; ni < 4; ++ni)
#pragma unroll
            for (int j = 0; j < 2; ++j) {
#pragma unroll
                for (int mk = 4; mk <= 16; mk <<= 1)
                    p[ni][j] += __shfl_xor_sync(0xFFFFFFFFu, p[ni][j], mk);
            }
        if (lane < 4) {
#pragma unroll
            for (int ni = 0; ni < 4; ++ni)
#pragma unroll
                for (int j = 0; j < 2; ++j)
                    atomicAdd(
                        out + (long)b * N_DIM + n0 + nwarp + ni * 8 + 2 * t + j,
                        p[ni][j]);
        }
    }
}

extern "C" void kernel_launch(void* const* d_in, const int* in_sizes, int n_in,
                              void* d_out, int out_size) {
    const float* x  = (const float*)d_in[0];  // (32,256,56,56)
    const float* Ws = (const float*)d_in[1];  // (1024,56,56)
    const float* Wd = (const float*)d_in[2];  // (1024,256,1,1)
    const float* Wb = (const float*)d_in[3];  // (1,1024)
    float* out = (float*)d_out;               // (32,1024)

    cudaFuncSetAttribute(gemm_kernel,
                         cudaFuncAttributeMaxDynamicSharedMemorySize, SMEM_TOTAL);

    const long total = (long)M_DIM * K_DIM + (long)N_DIM * K_DIM;
    conv_kernel<<<(int)((total / 4 + 255) / 256), 256>>>(x, Ws);
    init_out_kernel<<<(32 * N_DIM) / 256, 256>>>(Wb, out);

    gemm_kernel<<<NCTAS, 256, SMEM_TOTAL>>>(Wd, out);
}

// round 11
// speedup vs baseline: 1.0469x; 1.0469x over previous
#include <cuda_runtime.h>
#include <cuda_fp16.h>
#include <cstdint>

// out[b,n] = sum_{c,hw} x[b,c,hw]*W_s[n,hw]*W_d[n,c] + W_b[n]
// GEMM Y[(b,c),n] = X[8192,3136] @ Ws[1024,3136]^T, single-fp16 mma.sync,
// fp32 accum, fused W_d epilogue, K-split 4 via atomicAdd merge.
// R9: revert to R7 grid-strided gemm (R8 persistent regressed -> in-tile
// bound, not fixed-cost bound). Speed up the fp32->fp16 convert pass
// (8 elem/thread, 16B stores) and fuse the bias init into it.

#define K_DIM 3136
#define C_DIM 256
#define N_DIM 1024
#define M_DIM 8192
#define BM 128
#define BN 128
#define BK 64
#define KSPLIT 4
#define MAT_B 16384           // 128 rows * 128B
#define STAGE_B 32768         // A + B
#define SMEM_TOTAL (3 * STAGE_B)   // 98304

// ---------------- scratch (alloc-free) ----------------
__device__ __align__(256) __half g_X16[(long)M_DIM * K_DIM];
__device__ __align__(256) __half g_W16[(long)N_DIM * K_DIM];

__device__ __forceinline__ uint32_t smem_u32(const void* p) {
    uint32_t a;
    asm("{ .reg .u64 t; cvta.to.shared.u64 t, %1; cvt.u32.u64 %0, t; }"
        : "=r"(a) : "l"(p));
    return a;
}
__device__ __forceinline__ void cp_async16(uint32_t dst, const void* src) {
    asm volatile("cp.async.cg.shared.global [%0], [%1], 16;"
                 :: "r"(dst), "l"(src));
}
__device__ __forceinline__ void cp_commit() {
    asm volatile("cp.async.commit_group;" ::: "memory");
}
template <int N>
__device__ __forceinline__ void cp_wait() {
    asm volatile("cp.async.wait_group %0;" :: "n"(N) : "memory");
}
__device__ __forceinline__ void ldsm4(uint32_t& r0, uint32_t& r1, uint32_t& r2,
                                      uint32_t& r3, uint32_t a) {
    asm volatile("ldmatrix.sync.aligned.m8n8.x4.shared.b16 {%0,%1,%2,%3}, [%4];"
                 : "=r"(r0), "=r"(r1), "=r"(r2), "=r"(r3) : "r"(a));
}
__device__ __forceinline__ void mma16816(float* c, const uint32_t* a,
                                         const uint32_t* b) {
    asm volatile(
        "mma.sync.aligned.m16n8k16.row.col.f32.f16.f16.f32 "
        "{%0,%1,%2,%3}, {%4,%5,%6,%7}, {%8,%9}, {%0,%1,%2,%3};"
        : "+f"(c[0]), "+f"(c[1]), "+f"(c[2]), "+f"(c[3])
        : "r"(a[0]), "r"(a[1]), "r"(a[2]), "r"(a[3]), "r"(b[0]), "r"(b[1]));
}

// ---------------- fused convert (8 elem/thread, 16B stores) + bias init ----
__device__ __forceinline__ uint4 cvt8(const float* __restrict__ s) {
    float4 v0 = *(const float4*)s;
    float4 v1 = *(const float4*)(s + 4);
    __half2 h0 = __floats2half2_rn(v0.x, v0.y);
    __half2 h1 = __floats2half2_rn(v0.z, v0.w);
    __half2 h2 = __floats2half2_rn(v1.x, v1.y);
    __half2 h3 = __floats2half2_rn(v1.z, v1.w);
    uint4 r;
    r.x = *(const uint32_t*)&h0; r.y = *(const uint32_t*)&h1;
    r.z = *(const uint32_t*)&h2; r.w = *(const uint32_t*)&h3;
    return r;
}

__global__ void prep_kernel(const float* __restrict__ x,
                            const float* __restrict__ ws,
                            const float* __restrict__ wb,
                            float* __restrict__ out) {
    const long NX = (long)M_DIM * K_DIM;
    const long NW = (long)N_DIM * K_DIM;
    long i = ((long)blockIdx.x * blockDim.x + threadIdx.x) * 8;
    if (i < NX) {
        *(uint4*)(g_X16 + i) = cvt8(x + i);
    } else if (i < NX + NW) {
        long j = i - NX;
        *(uint4*)(g_W16 + j) = cvt8(ws + j);
    } else if (i < NX + NW + 32L * N_DIM) {
        long j = i - NX - NW;             // 0 .. 32767, 8 at a time
        int nb = (int)(j & (N_DIM - 1));  // 8-aligned, N_DIM divides row
        float4 b0 = *(const float4*)(wb + nb);
        float4 b1 = *(const float4*)(wb + nb + 4);
        *(float4*)(out + j) = b0;
        *(float4*)(out + j + 4) = b1;
    }
}

// ---------------- main GEMM (identical to R7 measured-best) ----------------
// smem swizzle: 16B chunk c of row r lives at r*128 + ((c ^ (r&7))<<4).
__global__ __launch_bounds__(256, 2)
void gemm_kernel(const float* __restrict__ Wd, float* __restrict__ out) {
    extern __shared__ char smem[];
    const uint32_t sb = smem_u32(smem);
    const int tid = threadIdx.x;
    const int lane = tid & 31;
    const int warp = tid >> 5;
    const int m0 = blockIdx.y * BM;
    const int n0 = blockIdx.x * BN;
    const int mwarp = (warp >> 2) * 64;   // 2 warp-rows
    const int nwarp = (warp & 3) * 32;    // 4 warp-cols

    // K-split range: boundaries 0,13,25,37,49
    const int z = blockIdx.z;
    const int cs = (z == 0) ? 0 : 13 + 12 * (z - 1);
    const int ce = 13 + 12 * z;           // exclusive
    const int nch = ce - cs;

    float acc[4][4][4];
#pragma unroll
    for (int i = 0; i < 4; ++i)
#pragma unroll
        for (int j = 0; j < 4; ++j)
#pragma unroll
            for (int k = 0; k < 4; ++k) acc[i][j][k] = 0.f;

    const uint32_t e = (uint32_t)(lane & 7);          // swizzle key
    const uint32_t a_row = (uint32_t)(mwarp + (lane & 15)) * 128u;
    const uint32_t b_row =
        (uint32_t)(nwarp + (lane & 7) + ((lane >> 4) & 1) * 8) * 128u;
    uint32_t akoff[4], bkoff[4];
#pragma unroll
    for (int ks = 0; ks < 4; ++ks) {
        akoff[ks] = (((uint32_t)(ks * 2 + (lane >> 4)) ^ e) << 4);
        bkoff[ks] = (((uint32_t)(ks * 2 + ((lane >> 3) & 1)) ^ e) << 4);
    }

    auto load_chunk = [&](int chunk, int s) {
        const long k0 = (long)chunk * BK;
        const uint32_t st = sb + (uint32_t)s * STAGE_B;
#pragma unroll
        for (int u = 0; u < 4; ++u) {
            const int lin = tid + u * 256;
            const int row = lin >> 3;
            const uint32_t c = (uint32_t)(lin & 7);
            const uint32_t soff =
                (uint32_t)(row * 128) + (((c ^ (uint32_t)(row & 7))) << 4);
            cp_async16(st + soff,
                       g_X16 + (long)(m0 + row) * K_DIM + k0 + c * 8);
            cp_async16(st + MAT_B + soff,
                       g_W16 + (long)(n0 + row) * K_DIM + k0 + c * 8);
        }
    };

    load_chunk(cs, 0); cp_commit();
    load_chunk(cs + 1, 1); cp_commit();

    for (int i = 0; i < nch; ++i) {
        if (i == nch - 1) cp_wait<0>(); else cp_wait<1>();
        __syncthreads();   // chunk i visible; all warps done with chunk i-1
        if (i + 2 < nch) {
            load_chunk(cs + i + 2, (i + 2) % 3);
            cp_commit();
        }

        const uint32_t st = sb + (uint32_t)(i % 3) * STAGE_B;
        const uint32_t Ab = st + a_row;
        const uint32_t Bb = st + MAT_B + b_row;
#pragma unroll
        for (int ks = 0; ks < 4; ++ks) {
            uint32_t a[4][4], b[4][2];
#pragma unroll
            for (int mi = 0; mi < 4; ++mi)
                ldsm4(a[mi][0], a[mi][1], a[mi][2], a[mi][3],
                      Ab + (uint32_t)(mi * 16 * 128) + akoff[ks]);
#pragma unroll
            for (int seg = 0; seg < 2; ++seg)
                ldsm4(b[2 * seg][0], b[2 * seg][1], b[2 * seg + 1][0],
                      b[2 * seg + 1][1],
                      Bb + (uint32_t)(seg * 16 * 128) + bkoff[ks]);
#pragma unroll
            for (int mi = 0; mi < 4; ++mi)
#pragma unroll
                for (int ni = 0; ni < 4; ++ni)
                    mma16816(acc[mi][ni], a[mi], b[ni]);
        }
    }

    // ---------------- fused epilogue (partial over this z's K range) --------
    const int b = m0 >> 8;
    const int cbase = (m0 & (C_DIM - 1)) + mwarp;
    const int g = lane >> 2;
    const int t = lane & 3;

    float p[4][2];
#pragma unroll
    for (int ni = 0; ni < 4; ++ni) { p[ni][0] = 0.f; p[ni][1] = 0.f; }

#pragma unroll
    for (int mi = 0; mi < 4; ++mi) {
        const int c0 = cbase + mi * 16 + g;
#pragma unroll
        for (int ni = 0; ni < 4; ++ni) {
            const int n = n0 + nwarp + ni * 8 + 2 * t;
#pragma unroll
            for (int j = 0; j < 2; ++j) {
                const float w0 = __ldg(Wd + (long)(n + j) * C_DIM + c0);
                const float w1 = __ldg(Wd + (long)(n + j) * C_DIM + c0 + 8);
                p[ni][j] += acc[mi][ni][j] * w0 + acc[mi][ni][j + 2] * w1;
            }
        }
    }
#pragma unroll
    for (int ni = 0; ni < 4; ++ni)
#pragma unroll
        for (int j = 0; j < 2; ++j) {
#pragma unroll
            for (int mk = 4; mk <= 16; mk <<= 1)
                p[ni][j] += __shfl_xor_sync(0xFFFFFFFFu, p[ni][j], mk);
        }
    if (lane < 4) {
#pragma unroll
        for (int ni = 0; ni < 4; ++ni)
#pragma unroll
            for (int j = 0; j < 2; ++j)
                atomicAdd(out + (long)b * N_DIM + n0 + nwarp + ni * 8 + 2 * t + j,
                          p[ni][j]);
    }
}

extern "C" void kernel_launch(void* const* d_in, const int* in_sizes, int n_in,
                              void* d_out, int out_size) {
    const float* x  = (const float*)d_in[0];  // (32,256,56,56)
    const float* Ws = (const float*)d_in[1];  // (1024,56,56)
    const float* Wd = (const float*)d_in[2];  // (1024,256,1,1)
    const float* Wb = (const float*)d_in[3];  // (1,1024)
    float* out = (float*)d_out;               // (32,1024)

    cudaFuncSetAttribute(gemm_kernel,
                         cudaFuncAttributeMaxDynamicSharedMemorySize, SMEM_TOTAL);

    const long total =
        (long)M_DIM * K_DIM + (long)N_DIM * K_DIM + 32L * N_DIM;
    prep_kernel<<<(int)((total / 8 + 255) / 256), 256>>>(x, Ws, Wb, out);

    dim3 grid(N_DIM / BN, M_DIM / BM, KSPLIT);  // (8, 64, 4)
    gemm_kernel<<<grid, 256, SMEM_TOTAL>>>(Wd, out);
}